// round 17
// baseline (speedup 1.0000x reference)
#include <cuda_runtime.h>
#include <cuda_bf16.h>
#include <cstdint>

#define S 1024
#define B 8192
#define EPSF 1e-8f
#define THREADS 256
#define SEG 128              // timesteps per warp segment
#define LPT 4                // timesteps per lane
#define WPR 8                // warps per row
#define NBLK B               // 1 row per block

__device__ float g_ga[S];   // gamma*lam
__device__ float g_gb[S];   // gamma*(1-lam)

// accurate tanh: rel err ~1e-7
__device__ __forceinline__ float tanh_acc(float x) {
    float e = __expf(2.0f * x);
    return 1.0f - __fdividef(2.0f, e + 1.0f);
}

__device__ __forceinline__ void cp_async4(void* smem_dst, const void* gmem_src) {
    unsigned int s = (unsigned int)__cvta_generic_to_shared(smem_dst);
    asm volatile("cp.async.ca.shared.global [%0], [%1], 4;" :: "r"(s), "l"(gmem_src));
}

// ---- setup: tables once; signal dependents as soon as writes are visible ----
__global__ void setup_kernel(const float* __restrict__ raw_gamma,
                             const float* __restrict__ raw_lambd)
{
    const float gamma = fmaxf(tanh_acc(raw_gamma[0]), EPSF);
    int i = threadIdx.x;
    float lam = fmaxf(tanh_acc(raw_lambd[i]), EPSF);
    g_ga[i] = gamma * lam;
    g_gb[i] = gamma * (1.0f - lam);
    __threadfence();
    asm volatile("griddepcontrol.launch_dependents;");
}

// Two-level parallel reverse affine scan: 8 warps per row, 128-step segment
// per warp, 4 timesteps per lane. PDL: starts while setup runs; waits on the
// grid dependency only right before reading the tables.
__global__ __launch_bounds__(THREADS, 8)
void td_lambda_kernel(const float* __restrict__ values,
                      const float* __restrict__ rewards,
                      const int*   __restrict__ dones,
                      float* __restrict__ out)
{
    __shared__ float s_v[WPR][SEG + SEG / 32];   // 8 x 132, padded (33-stride)
    __shared__ float s_cA[WPR], s_cB[WPR];
    __shared__ float s_part[THREADS];            // srw scratch

    const int tid  = threadIdx.x;
    const int lane = tid & 31;
    const int warp = tid >> 5;

    if (blockIdx.x < NBLK) {
        const int b   = blockIdx.x;
        const int seg = warp;                    // 0..7
        const float* __restrict__ rrow = rewards + (size_t)b * S;
        const int*   __restrict__ drow = dones   + (size_t)b * S;
        const float* __restrict__ vrow = values  + (size_t)b * (S + 1);
        float* __restrict__ orow = out + (size_t)b * S;

        const int segbase = seg * SEG;
        const int base    = segbase + lane * LPT;

        // ---- table-independent loads first (overlap with setup kernel) ----
        #pragma unroll
        for (int k = 0; k < 4; ++k)
            cp_async4(&s_v[warp][lane + 33 * k],
                      vrow + segbase + 1 + lane + 32 * k);
        asm volatile("cp.async.commit_group;");

        float4 r4 = __ldcs((const float4*)(rrow + base));
        int4   d4 = __ldcs((const int4*)(drow + base));
        const float vS = __ldg(&vrow[S]);

        // ---- wait for setup's table writes, then read tables ----
        asm volatile("griddepcontrol.wait;" ::: "memory");
        float4 ga4 = *(const float4*)(g_ga + base);
        float4 gb4 = *(const float4*)(g_gb + base);

        asm volatile("cp.async.wait_group 0;");
        __syncwarp();

        float r[LPT]  = {r4.x, r4.y, r4.z, r4.w};
        int   dn[LPT] = {d4.x, d4.y, d4.z, d4.w};
        float ga[LPT] = {ga4.x, ga4.y, ga4.z, ga4.w};
        float gb[LPT] = {gb4.x, gb4.y, gb4.z, gb4.w};
        // conflict-free scalar reads: bank(4l + l>>3) distinct over lanes
        const float* vbuf = &s_v[warp][lane * LPT + (lane >> 3)];

        float a[LPT], bb[LPT];
        #pragma unroll
        for (int j = 0; j < LPT; ++j) {
            float v = vbuf[j];
            bool  z = (dn[j] != 0);
            a[j]  = z ? 0.0f : ga[j];
            bb[j] = z ? r[j] : fmaf(gb[j], v, r[j]);
        }

        // local composition G = F_j0 ∘ ... ∘ F_j3
        float A = a[LPT - 1], Bc = bb[LPT - 1];
        #pragma unroll
        for (int j = LPT - 2; j >= 0; --j) {
            Bc = fmaf(a[j], Bc, bb[j]);
            A  = a[j] * A;
        }

        // warp suffix scan of lane composites
        float sA = A, sB = Bc;
        #pragma unroll
        for (int off = 1; off < 32; off <<= 1) {
            float a2 = __shfl_down_sync(0xffffffffu, sA, off);
            float b2 = __shfl_down_sync(0xffffffffu, sB, off);
            if (lane + off < 32) {
                sB = fmaf(sA, b2, sB);
                sA = sA * a2;
            }
        }

        if (lane == 0) { s_cA[warp] = sA; s_cB[warp] = sB; }
        __syncthreads();

        // entry carry: apply composites of segments seg+1..7 to v_S
        float carry = vS;
        #pragma unroll
        for (int k = WPR - 1; k >= 1; --k) {
            if (k > seg)
                carry = fmaf(s_cA[k], carry, s_cB[k]);
        }

        float eA = __shfl_down_sync(0xffffffffu, sA, 1);
        float eB = __shfl_down_sync(0xffffffffu, sB, 1);
        if (lane == 31) { eA = 1.0f; eB = 0.0f; }
        float x = fmaf(eA, carry, eB);

        float o[LPT];
        #pragma unroll
        for (int j = LPT - 1; j >= 0; --j) {
            x = fmaf(a[j], x, bb[j]);
            o[j] = x;
        }
        __stcs((float4*)(orow + base), make_float4(o[0], o[1], o[2], o[3]));
    } else {
        // ---------------- srw (sum_reward_weights) ----------------
        float* s_w = &s_v[0][0];   // 1056 contiguous floats >= S

        asm volatile("griddepcontrol.wait;" ::: "memory");

        if (tid < 32) {
            float carry = 1.0f;
            for (int c = S / 32 - 1; c >= 0; --c) {
                const int t = c * 32 + lane;
                float a  = g_ga[t];
                float bb = g_gb[t];
                #pragma unroll
                for (int off = 1; off < 32; off <<= 1) {
                    float a2 = __shfl_down_sync(0xffffffffu, a,  off);
                    float b2 = __shfl_down_sync(0xffffffffu, bb, off);
                    if (lane + off < 32) {
                        bb = fmaf(a, b2, bb);
                        a  = a * a2;
                    }
                }
                float vv = fmaf(a, carry, bb);
                s_w[t] = fmaxf(1.0f - vv, EPSF);
                carry = __shfl_sync(0xffffffffu, vv, 0);
            }
        }
        __syncthreads();

        float ps = 0.0f;
        for (int i = tid; i < S; i += THREADS) ps += s_w[i];
        s_part[tid] = ps;
        __syncthreads();
        for (int stride = THREADS / 2; stride > 0; stride >>= 1) {
            if (tid < stride) s_part[tid] += s_part[tid + stride];
            __syncthreads();
        }
        float mean = s_part[0] * (1.0f / (float)S);
        float inv  = 1.0f / fmaxf(mean, EPSF);
        for (int i = tid; i < S; i += THREADS)
            out[(size_t)B * S + i] = s_w[i] * inv;
    }
}

extern "C" void kernel_launch(void* const* d_in, const int* in_sizes, int n_in,
                              void* d_out, int out_size) {
    const float* raw_gamma = (const float*)d_in[0];
    const float* raw_lambd = (const float*)d_in[1];
    const float* values    = (const float*)d_in[2];
    const float* rewards   = (const float*)d_in[3];
    const int*   dones     = (const int*)d_in[4];
    float* out = (float*)d_out;

    setup_kernel<<<1, S>>>(raw_gamma, raw_lambd);

    // PDL: main kernel may launch while setup is running; it synchronizes
    // internally via griddepcontrol.wait before reading the tables.
    cudaLaunchConfig_t cfg = {};
    cfg.gridDim  = dim3(NBLK + 1);
    cfg.blockDim = dim3(THREADS);
    cudaLaunchAttribute attr[1];
    attr[0].id = cudaLaunchAttributeProgrammaticStreamSerialization;
    attr[0].val.programmaticStreamSerializationAllowed = 1;
    cfg.attrs = attr;
    cfg.numAttrs = 1;
    cudaLaunchKernelEx(&cfg, td_lambda_kernel, values, rewards, dones, (float*)out);
}